// round 10
// baseline (speedup 1.0000x reference)
#include <cuda_runtime.h>
#include <math.h>
#include <stdint.h>

// DimeNet interaction fragment on the fixed circular graph from setup_inputs.
// Round 10: R9 with the copysign identity FIXED:
//   m = pi/2 - 2*at >= 0;  alpha = pi/2 - copysign(m, den - cn)
//   (den>cn -> 2*at ; den<cn -> pi - 2*at)
// Keeps: f32x2 k-pair packing, launch_bounds(256,6) for 6 blocks/SM,
// 16B-aligned rbf rows, column-duplicated literal-offset smem.

#define N_ATOMS 32768
#define ATOM_MASK (N_ATOMS - 1)
#define APB 16
#define PI_F   3.14159265358979323846f
#define PI_2_F 1.57079632679489661923f

static __device__ __forceinline__ uint64_t pk2(float lo, float hi) {
    uint64_t r; asm("mov.b64 %0, {%1, %2};" : "=l"(r) : "f"(lo), "f"(hi)); return r;
}
static __device__ __forceinline__ void upk2(uint64_t v, float& lo, float& hi) {
    asm("mov.b64 {%0, %1}, %2;" : "=f"(lo), "=f"(hi) : "l"(v));
}
static __device__ __forceinline__ uint64_t mul2(uint64_t a, uint64_t b) {
    uint64_t d; asm("mul.rn.f32x2 %0, %1, %2;" : "=l"(d) : "l"(a), "l"(b)); return d;
}
static __device__ __forceinline__ uint64_t fma2(uint64_t a, uint64_t b, uint64_t c) {
    uint64_t d; asm("fma.rn.f32x2 %0, %1, %2, %3;" : "=l"(d) : "l"(a), "l"(b), "l"(c)); return d;
}
static __device__ __forceinline__ void fma2a(uint64_t& d, uint64_t a, uint64_t b) {
    asm("fma.rn.f32x2 %0, %1, %2, %0;" : "+l"(d) : "l"(a), "l"(b));
}

__global__ __launch_bounds__(256, 6)
void dimenet_pk6_kernel(const float* __restrict__ xyz, float* __restrict__ out) {
    // column-duplicated scalar tiles: row r holds data of column (r & 15)
    __shared__ float4 s_r4[APB][32];          // {rx,ry,rz,d}        8 KB
    __shared__ float  s_rbf[APB][32][8];      // rbf rows, 16B pad  16 KB

    const int tid = threadIdx.x;
    const int a = tid >> 4;
    const int c = tid & 15;
    const int j = blockIdx.x * APB + a;

    const int off = (c < 8) ? (c + 1) : (N_ATOMS - (c - 7));
    const int nb  = (j + off) & ATOM_MASK;

    const float jx = xyz[3 * j + 0];
    const float jy = xyz[3 * j + 1];
    const float jz = xyz[3 * j + 2];
    const float px = xyz[3 * nb + 0];
    const float py = xyz[3 * nb + 1];
    const float pz = xyz[3 * nb + 2];

    const float rx = px - jx, ry = py - jy, rz = pz - jz;
    const float nrx = jx - px, nry = jy - py, nrz = jz - pz;   // exact negation

    const float d2 = fmaf(rx, rx, fmaf(ry, ry, rz * rz));
    const float d  = d2 * rsqrtf(d2);
    const float4 my4 = make_float4(rx, ry, rz, d);
    s_r4[a][c] = my4;
    s_r4[a][c + 16] = my4;

    // radial basis (env-prescaled Chebyshev recurrence)
    const float x   = d * 0.2f;
    const float x2  = x * x;
    const float x5  = x2 * x2 * x;
    const float env = __fdividef(1.0f, x) + x5 * fmaf(x, fmaf(-21.0f, x, 48.0f), -28.0f);
    float sn, cs;
    __sincosf(PI_F * x, &sn, &cs);
    const float twoc = cs + cs;
    const float e1 = env * sn;
    const float e2 = twoc * e1;
    const float e3 = fmaf(twoc, e2, -e1);
    const float e4 = fmaf(twoc, e3, -e2);
    const float e5 = fmaf(twoc, e4, -e3);
    const float e6 = fmaf(twoc, e5, -e4);
    {
        float4* w  = (float4*)&s_rbf[a][c][0];
        float4* w2 = (float4*)&s_rbf[a][c + 16][0];
        const float4 f0 = make_float4(e1, e2, e3, e4);
        const float4 f1 = make_float4(e5, e6, 0.0f, 0.0f);
        w[0] = f0;  w[1] = f1;
        w2[0] = f0; w2[1] = f1;
    }

    __syncwarp();   // produced & consumed within the same half-warp

    // splatted r1 for packed geometry
    const uint64_t RX = pk2(rx, rx),  RY = pk2(ry, ry),  RZ = pk2(rz, rz);
    const uint64_t NX = pk2(nrx, nrx), NY = pk2(nry, nry), NZ = pk2(nrz, nrz);
    const uint64_t DD = pk2(d, d);

    // degree-9 minimax atan coefficients (packed)
    const uint64_t K0 = pk2( 0.9998660f,  0.9998660f);
    const uint64_t K1 = pk2(-0.3302995f, -0.3302995f);
    const uint64_t K2 = pk2( 0.1801410f,  0.1801410f);
    const uint64_t K3 = pk2(-0.0851330f, -0.0851330f);
    const uint64_t K4 = pk2( 0.0208351f,  0.0208351f);

    const float4*   rp   = &s_r4[a][c];                       // partner +k = rp[k]
    const uint64_t* rbfb = (const uint64_t*)&s_rbf[a][c][0];  // row +k = rbfb + 4k

    uint64_t acc0 = 0ull, acc1 = 0ull, acc2 = 0ull;           // packed over rbf comps

    #pragma unroll
    for (int k = 1; k <= 4; k++) {
        const int k2 = k + 4;                                 // 5..8
        const float4 b1 = rp[k];
        const float4 b2 = rp[k2];
        const uint64_t BX = pk2(b1.x, b2.x);
        const uint64_t BY = pk2(b1.y, b2.y);
        const uint64_t BZ = pk2(b1.z, b2.z);
        const uint64_t BD = pk2(b1.w, b2.w);

        const uint64_t DOT = fma2(RZ, BZ, fma2(RY, BY, mul2(RX, BX)));
        const uint64_t CX  = fma2(RY, BZ, mul2(NZ, BY));
        const uint64_t CY  = fma2(RZ, BX, mul2(NX, BZ));
        const uint64_t CZ  = fma2(RX, BY, mul2(NY, BX));
        const uint64_t CC  = fma2(CX, CX, fma2(CY, CY, mul2(CZ, CZ)));
        const uint64_t DEN = fma2(DD, BD, DOT);               // >= 0

        float cc1, cc2v, den1, den2v;
        upk2(CC, cc1, cc2v);
        upk2(DEN, den1, den2v);
        cc1  = fmaxf(cc1, 1e-30f);
        cc2v = fmaxf(cc2v, 1e-30f);
        const float cn1 = cc1 * rsqrtf(cc1);
        const float cn2 = cc2v * rsqrtf(cc2v);
        const float q1 = __fdividef(fminf(cn1, den1), fmaxf(cn1, den1));
        const float q2 = __fdividef(fminf(cn2, den2v), fmaxf(cn2, den2v));

        const uint64_t Q = pk2(q1, q2);
        const uint64_t Z = mul2(Q, Q);
        uint64_t P = fma2(K4, Z, K3);
        P = fma2(P, Z, K2);
        P = fma2(P, Z, K1);
        P = fma2(P, Z, K0);
        const uint64_t AT = mul2(P, Q);

        float at1, at2;
        upk2(AT, at1, at2);
        // m = pi/2 - 2*at >= 0 ;  alpha = pi/2 - copysign(m, den - cn)
        //   den>cn -> pi/2 - m = 2*at ;  den<cn -> pi/2 + m = pi - 2*at
        const float m1 = fmaf(-2.0f, at1, PI_2_F);
        const float m2 = fmaf(-2.0f, at2, PI_2_F);
        const float al1 = PI_2_F - copysignf(m1, den1 - cn1);
        const float al2 = PI_2_F - copysignf(m2, den2v - cn2);

        // own contributions: rows c+k and c+k2 (literal offsets, 16B-aligned)
        {
            const uint64_t s1 = pk2(al1, al1);
            fma2a(acc0, s1, rbfb[4 * k + 0]);
            fma2a(acc1, s1, rbfb[4 * k + 1]);
            fma2a(acc2, s1, rbfb[4 * k + 2]);
            const uint64_t s2 = pk2(al2, al2);
            fma2a(acc0, s2, rbfb[4 * k2 + 0]);
            fma2a(acc1, s2, rbfb[4 * k2 + 1]);
            fma2a(acc2, s2, rbfb[4 * k2 + 2]);
        }
        // mirror for k: alpha(c-k,c) from lane c-k, row c-k = dup row c+16-k
        {
            const float alm = __shfl_sync(0xFFFFFFFFu, al1, (c - k) & 15, 16);
            const uint64_t sm = pk2(alm, alm);
            fma2a(acc0, sm, rbfb[4 * (16 - k) + 0]);
            fma2a(acc1, sm, rbfb[4 * (16 - k) + 1]);
            fma2a(acc2, sm, rbfb[4 * (16 - k) + 2]);
        }
        // mirror for k2 (k2 == 8 pair is self-mirrored)
        if (k2 < 8) {
            const float alm = __shfl_sync(0xFFFFFFFFu, al2, (c - k2) & 15, 16);
            const uint64_t sm = pk2(alm, alm);
            fma2a(acc0, sm, rbfb[4 * (16 - k2) + 0]);
            fma2a(acc1, sm, rbfb[4 * (16 - k2) + 1]);
            fma2a(acc2, sm, rbfb[4 * (16 - k2) + 2]);
        }
    }

    uint64_t* o = (uint64_t*)(out + (size_t)(j * 16 + c) * 6);
    o[0] = acc0;
    o[1] = acc1;
    o[2] = acc2;
}

extern "C" void kernel_launch(void* const* d_in, const int* in_sizes, int n_in,
                              void* d_out, int out_size) {
    const float* xyz = (const float*)d_in[0];
    float* out = (float*)d_out;
    (void)in_sizes; (void)n_in; (void)out_size;
    dimenet_pk6_kernel<<<N_ATOMS / APB, 256>>>(xyz, out);
}

// round 11
// speedup vs baseline: 1.0889x; 1.0889x over previous
#include <cuda_runtime.h>
#include <math.h>
#include <stdint.h>

// DimeNet interaction fragment on the fixed circular graph from setup_inputs.
// Round 11: R8 (f32x2 k-pair packing, natural regs ~44, 5 blocks/SM) plus
// 16B-padded rbf rows (LDS.128+LDS.64 per row) and the corrected branch-free
// copysign alpha finalization. NO register cap (R10's (256,6) cap spilled).

#define N_ATOMS 32768
#define ATOM_MASK (N_ATOMS - 1)
#define APB 16
#define PI_F   3.14159265358979323846f
#define PI_2_F 1.57079632679489661923f

static __device__ __forceinline__ uint64_t pk2(float lo, float hi) {
    uint64_t r; asm("mov.b64 %0, {%1, %2};" : "=l"(r) : "f"(lo), "f"(hi)); return r;
}
static __device__ __forceinline__ void upk2(uint64_t v, float& lo, float& hi) {
    asm("mov.b64 {%0, %1}, %2;" : "=f"(lo), "=f"(hi) : "l"(v));
}
static __device__ __forceinline__ uint64_t mul2(uint64_t a, uint64_t b) {
    uint64_t d; asm("mul.rn.f32x2 %0, %1, %2;" : "=l"(d) : "l"(a), "l"(b)); return d;
}
static __device__ __forceinline__ uint64_t fma2(uint64_t a, uint64_t b, uint64_t c) {
    uint64_t d; asm("fma.rn.f32x2 %0, %1, %2, %3;" : "=l"(d) : "l"(a), "l"(b), "l"(c)); return d;
}
static __device__ __forceinline__ void fma2a(uint64_t& d, uint64_t a, uint64_t b) {
    asm("fma.rn.f32x2 %0, %1, %2, %0;" : "+l"(d) : "l"(a), "l"(b));
}

__global__ __launch_bounds__(256)
void dimenet_r11_kernel(const float* __restrict__ xyz, float* __restrict__ out) {
    // column-duplicated scalar tiles: row r holds data of column (r & 15)
    __shared__ float4 s_r4[APB][32];          // {rx,ry,rz,d}        8 KB
    __shared__ float  s_rbf[APB][32][8];      // rbf rows, 16B pad  16 KB

    const int tid = threadIdx.x;
    const int a = tid >> 4;
    const int c = tid & 15;
    const int j = blockIdx.x * APB + a;

    const int off = (c < 8) ? (c + 1) : (N_ATOMS - (c - 7));
    const int nb  = (j + off) & ATOM_MASK;

    const float jx = xyz[3 * j + 0];
    const float jy = xyz[3 * j + 1];
    const float jz = xyz[3 * j + 2];
    const float px = xyz[3 * nb + 0];
    const float py = xyz[3 * nb + 1];
    const float pz = xyz[3 * nb + 2];

    const float rx = px - jx, ry = py - jy, rz = pz - jz;
    const float nrx = jx - px, nry = jy - py, nrz = jz - pz;   // exact negation

    const float d2 = fmaf(rx, rx, fmaf(ry, ry, rz * rz));
    const float d  = d2 * rsqrtf(d2);
    const float4 my4 = make_float4(rx, ry, rz, d);
    s_r4[a][c] = my4;
    s_r4[a][c + 16] = my4;

    // radial basis (env-prescaled Chebyshev recurrence)
    const float x   = d * 0.2f;
    const float x2  = x * x;
    const float x5  = x2 * x2 * x;
    const float env = __fdividef(1.0f, x) + x5 * fmaf(x, fmaf(-21.0f, x, 48.0f), -28.0f);
    float sn, cs;
    __sincosf(PI_F * x, &sn, &cs);
    const float twoc = cs + cs;
    const float e1 = env * sn;
    const float e2 = twoc * e1;
    const float e3 = fmaf(twoc, e2, -e1);
    const float e4 = fmaf(twoc, e3, -e2);
    const float e5 = fmaf(twoc, e4, -e3);
    const float e6 = fmaf(twoc, e5, -e4);
    {
        float4* w  = (float4*)&s_rbf[a][c][0];
        float4* w2 = (float4*)&s_rbf[a][c + 16][0];
        const float4 f0 = make_float4(e1, e2, e3, e4);
        const float4 f1 = make_float4(e5, e6, 0.0f, 0.0f);
        w[0] = f0;  w[1] = f1;
        w2[0] = f0; w2[1] = f1;
    }

    __syncwarp();   // produced & consumed within the same half-warp

    // splatted r1 for packed geometry
    const uint64_t RX = pk2(rx, rx),  RY = pk2(ry, ry),  RZ = pk2(rz, rz);
    const uint64_t NX = pk2(nrx, nrx), NY = pk2(nry, nry), NZ = pk2(nrz, nrz);
    const uint64_t DD = pk2(d, d);

    // degree-9 minimax atan coefficients (packed)
    const uint64_t K0 = pk2( 0.9998660f,  0.9998660f);
    const uint64_t K1 = pk2(-0.3302995f, -0.3302995f);
    const uint64_t K2 = pk2( 0.1801410f,  0.1801410f);
    const uint64_t K3 = pk2(-0.0851330f, -0.0851330f);
    const uint64_t K4 = pk2( 0.0208351f,  0.0208351f);

    const float4*   rp   = &s_r4[a][c];                       // partner +k = rp[k]
    const uint64_t* rbfb = (const uint64_t*)&s_rbf[a][c][0];  // row +k = rbfb + 4k

    uint64_t acc0 = 0ull, acc1 = 0ull, acc2 = 0ull;           // packed over rbf comps

    #pragma unroll
    for (int k = 1; k <= 4; k++) {
        const int k2 = k + 4;                                 // 5..8
        const float4 b1 = rp[k];
        const float4 b2 = rp[k2];
        const uint64_t BX = pk2(b1.x, b2.x);
        const uint64_t BY = pk2(b1.y, b2.y);
        const uint64_t BZ = pk2(b1.z, b2.z);
        const uint64_t BD = pk2(b1.w, b2.w);

        const uint64_t DOT = fma2(RZ, BZ, fma2(RY, BY, mul2(RX, BX)));
        const uint64_t CX  = fma2(RY, BZ, mul2(NZ, BY));
        const uint64_t CY  = fma2(RZ, BX, mul2(NX, BZ));
        const uint64_t CZ  = fma2(RX, BY, mul2(NY, BX));
        const uint64_t CC  = fma2(CX, CX, fma2(CY, CY, mul2(CZ, CZ)));
        const uint64_t DEN = fma2(DD, BD, DOT);               // >= 0

        float cc1, cc2v, den1, den2v;
        upk2(CC, cc1, cc2v);
        upk2(DEN, den1, den2v);
        cc1  = fmaxf(cc1, 1e-30f);
        cc2v = fmaxf(cc2v, 1e-30f);
        const float cn1 = cc1 * rsqrtf(cc1);
        const float cn2 = cc2v * rsqrtf(cc2v);
        const float q1 = __fdividef(fminf(cn1, den1), fmaxf(cn1, den1));
        const float q2 = __fdividef(fminf(cn2, den2v), fmaxf(cn2, den2v));

        const uint64_t Q = pk2(q1, q2);
        const uint64_t Z = mul2(Q, Q);
        uint64_t P = fma2(K4, Z, K3);
        P = fma2(P, Z, K2);
        P = fma2(P, Z, K1);
        P = fma2(P, Z, K0);
        const uint64_t AT = mul2(P, Q);

        float at1, at2;
        upk2(AT, at1, at2);
        // m = pi/2 - 2*at >= 0 ;  alpha = pi/2 - copysign(m, den - cn)
        //   den>cn -> pi/2 - m = 2*at ;  den<cn -> pi/2 + m = pi - 2*at
        const float m1 = fmaf(-2.0f, at1, PI_2_F);
        const float m2 = fmaf(-2.0f, at2, PI_2_F);
        const float al1 = PI_2_F - copysignf(m1, den1 - cn1);
        const float al2 = PI_2_F - copysignf(m2, den2v - cn2);

        // own contributions: rows c+k and c+k2 (literal offsets, 16B-aligned)
        {
            const uint64_t s1 = pk2(al1, al1);
            fma2a(acc0, s1, rbfb[4 * k + 0]);
            fma2a(acc1, s1, rbfb[4 * k + 1]);
            fma2a(acc2, s1, rbfb[4 * k + 2]);
            const uint64_t s2 = pk2(al2, al2);
            fma2a(acc0, s2, rbfb[4 * k2 + 0]);
            fma2a(acc1, s2, rbfb[4 * k2 + 1]);
            fma2a(acc2, s2, rbfb[4 * k2 + 2]);
        }
        // mirror for k: alpha(c-k,c) from lane c-k, row c-k = dup row c+16-k
        {
            const float alm = __shfl_sync(0xFFFFFFFFu, al1, (c - k) & 15, 16);
            const uint64_t sm = pk2(alm, alm);
            fma2a(acc0, sm, rbfb[4 * (16 - k) + 0]);
            fma2a(acc1, sm, rbfb[4 * (16 - k) + 1]);
            fma2a(acc2, sm, rbfb[4 * (16 - k) + 2]);
        }
        // mirror for k2 (k2 == 8 pair is self-mirrored)
        if (k2 < 8) {
            const float alm = __shfl_sync(0xFFFFFFFFu, al2, (c - k2) & 15, 16);
            const uint64_t sm = pk2(alm, alm);
            fma2a(acc0, sm, rbfb[4 * (16 - k2) + 0]);
            fma2a(acc1, sm, rbfb[4 * (16 - k2) + 1]);
            fma2a(acc2, sm, rbfb[4 * (16 - k2) + 2]);
        }
    }

    uint64_t* o = (uint64_t*)(out + (size_t)(j * 16 + c) * 6);
    o[0] = acc0;
    o[1] = acc1;
    o[2] = acc2;
}

extern "C" void kernel_launch(void* const* d_in, const int* in_sizes, int n_in,
                              void* d_out, int out_size) {
    const float* xyz = (const float*)d_in[0];
    float* out = (float*)d_out;
    (void)in_sizes; (void)n_in; (void)out_size;
    dimenet_r11_kernel<<<N_ATOMS / APB, 256>>>(xyz, out);
}

// round 12
// speedup vs baseline: 1.1496x; 1.0557x over previous
#include <cuda_runtime.h>
#include <math.h>
#include <stdint.h>

// DimeNet interaction fragment on the fixed circular graph from setup_inputs.
// Round 12: exact R8 smem layout restored (24B rbf rows -> conflict-free banks;
// the R9-R11 32B padding caused 4-way conflicts, L1 78%, issue 35%). Adds the
// corrected copysign finalization and 128-thread blocks (11 blocks/SM, 44
// warps) for the latency-bound regime. f32x2 k-pair packing as in R8.

#define N_ATOMS 32768
#define ATOM_MASK (N_ATOMS - 1)
#define APB 8                       // atoms per 128-thread block
#define PI_F   3.14159265358979323846f
#define PI_2_F 1.57079632679489661923f

static __device__ __forceinline__ uint64_t pk2(float lo, float hi) {
    uint64_t r; asm("mov.b64 %0, {%1, %2};" : "=l"(r) : "f"(lo), "f"(hi)); return r;
}
static __device__ __forceinline__ void upk2(uint64_t v, float& lo, float& hi) {
    asm("mov.b64 {%0, %1}, %2;" : "=f"(lo), "=f"(hi) : "l"(v));
}
static __device__ __forceinline__ uint64_t mul2(uint64_t a, uint64_t b) {
    uint64_t d; asm("mul.rn.f32x2 %0, %1, %2;" : "=l"(d) : "l"(a), "l"(b)); return d;
}
static __device__ __forceinline__ uint64_t fma2(uint64_t a, uint64_t b, uint64_t c) {
    uint64_t d; asm("fma.rn.f32x2 %0, %1, %2, %3;" : "=l"(d) : "l"(a), "l"(b), "l"(c)); return d;
}
static __device__ __forceinline__ void fma2a(uint64_t& d, uint64_t a, uint64_t b) {
    asm("fma.rn.f32x2 %0, %1, %2, %0;" : "+l"(d) : "l"(a), "l"(b));
}

__global__ __launch_bounds__(128)
void dimenet_r12_kernel(const float* __restrict__ xyz, float* __restrict__ out) {
    // column-duplicated scalar tiles: row r holds data of column (r & 15)
    __shared__ float4 s_r4[APB][32];          // {rx,ry,rz,d}   4 KB
    __shared__ float  s_rbf[APB][32][6];      // 24B rows       6 KB (bank-clean)

    const int tid = threadIdx.x;
    const int a = tid >> 4;                   // atom slot 0..7
    const int c = tid & 15;                   // neighbor column
    const int j = blockIdx.x * APB + a;

    const int off = (c < 8) ? (c + 1) : (N_ATOMS - (c - 7));
    const int nb  = (j + off) & ATOM_MASK;

    const float jx = xyz[3 * j + 0];
    const float jy = xyz[3 * j + 1];
    const float jz = xyz[3 * j + 2];
    const float px = xyz[3 * nb + 0];
    const float py = xyz[3 * nb + 1];
    const float pz = xyz[3 * nb + 2];

    const float rx = px - jx, ry = py - jy, rz = pz - jz;
    const float nrx = jx - px, nry = jy - py, nrz = jz - pz;   // exact negation

    const float d2 = fmaf(rx, rx, fmaf(ry, ry, rz * rz));
    const float d  = d2 * rsqrtf(d2);
    const float4 my4 = make_float4(rx, ry, rz, d);
    s_r4[a][c] = my4;
    s_r4[a][c + 16] = my4;

    // radial basis (env-prescaled Chebyshev recurrence)
    const float x   = d * 0.2f;
    const float x2  = x * x;
    const float x5  = x2 * x2 * x;
    const float env = __fdividef(1.0f, x) + x5 * fmaf(x, fmaf(-21.0f, x, 48.0f), -28.0f);
    float sn, cs;
    __sincosf(PI_F * x, &sn, &cs);
    const float twoc = cs + cs;
    const float e1 = env * sn;
    const float e2 = twoc * e1;
    const float e3 = fmaf(twoc, e2, -e1);
    const float e4 = fmaf(twoc, e3, -e2);
    const float e5 = fmaf(twoc, e4, -e3);
    const float e6 = fmaf(twoc, e5, -e4);
    {
        float2* w  = (float2*)&s_rbf[a][c][0];
        float2* w2 = (float2*)&s_rbf[a][c + 16][0];
        const float2 f0 = make_float2(e1, e2);
        const float2 f1 = make_float2(e3, e4);
        const float2 f2 = make_float2(e5, e6);
        w[0] = f0;  w[1] = f1;  w[2] = f2;
        w2[0] = f0; w2[1] = f1; w2[2] = f2;
    }

    __syncwarp();   // produced & consumed within the same half-warp

    // splatted r1 for packed geometry
    const uint64_t RX = pk2(rx, rx),  RY = pk2(ry, ry),  RZ = pk2(rz, rz);
    const uint64_t NX = pk2(nrx, nrx), NY = pk2(nry, nry), NZ = pk2(nrz, nrz);
    const uint64_t DD = pk2(d, d);

    // degree-9 minimax atan coefficients (packed)
    const uint64_t K0 = pk2( 0.9998660f,  0.9998660f);
    const uint64_t K1 = pk2(-0.3302995f, -0.3302995f);
    const uint64_t K2 = pk2( 0.1801410f,  0.1801410f);
    const uint64_t K3 = pk2(-0.0851330f, -0.0851330f);
    const uint64_t K4 = pk2( 0.0208351f,  0.0208351f);

    const float4*   rp   = &s_r4[a][c];                       // partner +k = rp[k]
    const uint64_t* rbfb = (const uint64_t*)&s_rbf[a][c][0];  // row +k = rbfb + 3k

    uint64_t acc0 = 0ull, acc1 = 0ull, acc2 = 0ull;           // packed over rbf comps

    #pragma unroll
    for (int k = 1; k <= 4; k++) {
        const int k2 = k + 4;                                 // 5..8
        const float4 b1 = rp[k];
        const float4 b2 = rp[k2];
        const uint64_t BX = pk2(b1.x, b2.x);
        const uint64_t BY = pk2(b1.y, b2.y);
        const uint64_t BZ = pk2(b1.z, b2.z);
        const uint64_t BD = pk2(b1.w, b2.w);

        const uint64_t DOT = fma2(RZ, BZ, fma2(RY, BY, mul2(RX, BX)));
        const uint64_t CX  = fma2(RY, BZ, mul2(NZ, BY));
        const uint64_t CY  = fma2(RZ, BX, mul2(NX, BZ));
        const uint64_t CZ  = fma2(RX, BY, mul2(NY, BX));
        const uint64_t CC  = fma2(CX, CX, fma2(CY, CY, mul2(CZ, CZ)));
        const uint64_t DEN = fma2(DD, BD, DOT);               // >= 0

        float cc1, cc2v, den1, den2v;
        upk2(CC, cc1, cc2v);
        upk2(DEN, den1, den2v);
        cc1  = fmaxf(cc1, 1e-30f);
        cc2v = fmaxf(cc2v, 1e-30f);
        const float cn1 = cc1 * rsqrtf(cc1);
        const float cn2 = cc2v * rsqrtf(cc2v);
        const float q1 = __fdividef(fminf(cn1, den1), fmaxf(cn1, den1));
        const float q2 = __fdividef(fminf(cn2, den2v), fmaxf(cn2, den2v));

        const uint64_t Q = pk2(q1, q2);
        const uint64_t Z = mul2(Q, Q);
        uint64_t P = fma2(K4, Z, K3);
        P = fma2(P, Z, K2);
        P = fma2(P, Z, K1);
        P = fma2(P, Z, K0);
        const uint64_t AT = mul2(P, Q);

        float at1, at2;
        upk2(AT, at1, at2);
        // m = pi/2 - 2*at >= 0 ;  alpha = pi/2 - copysign(m, den - cn)
        //   den>cn -> pi/2 - m = 2*at ;  den<cn -> pi/2 + m = pi - 2*at
        const float m1 = fmaf(-2.0f, at1, PI_2_F);
        const float m2 = fmaf(-2.0f, at2, PI_2_F);
        const float al1 = PI_2_F - copysignf(m1, den1 - cn1);
        const float al2 = PI_2_F - copysignf(m2, den2v - cn2);

        // own contributions: rows c+k and c+k2 (literal offsets)
        {
            const uint64_t s1 = pk2(al1, al1);
            fma2a(acc0, s1, rbfb[3 * k + 0]);
            fma2a(acc1, s1, rbfb[3 * k + 1]);
            fma2a(acc2, s1, rbfb[3 * k + 2]);
            const uint64_t s2 = pk2(al2, al2);
            fma2a(acc0, s2, rbfb[3 * k2 + 0]);
            fma2a(acc1, s2, rbfb[3 * k2 + 1]);
            fma2a(acc2, s2, rbfb[3 * k2 + 2]);
        }
        // mirror for k: alpha(c-k,c) from lane c-k, row c-k = dup row c+16-k
        {
            const float alm = __shfl_sync(0xFFFFFFFFu, al1, (c - k) & 15, 16);
            const uint64_t sm = pk2(alm, alm);
            fma2a(acc0, sm, rbfb[3 * (16 - k) + 0]);
            fma2a(acc1, sm, rbfb[3 * (16 - k) + 1]);
            fma2a(acc2, sm, rbfb[3 * (16 - k) + 2]);
        }
        // mirror for k2 (k2 == 8 pair is self-mirrored)
        if (k2 < 8) {
            const float alm = __shfl_sync(0xFFFFFFFFu, al2, (c - k2) & 15, 16);
            const uint64_t sm = pk2(alm, alm);
            fma2a(acc0, sm, rbfb[3 * (16 - k2) + 0]);
            fma2a(acc1, sm, rbfb[3 * (16 - k2) + 1]);
            fma2a(acc2, sm, rbfb[3 * (16 - k2) + 2]);
        }
    }

    uint64_t* o = (uint64_t*)(out + (size_t)(j * 16 + c) * 6);
    o[0] = acc0;
    o[1] = acc1;
    o[2] = acc2;
}

extern "C" void kernel_launch(void* const* d_in, const int* in_sizes, int n_in,
                              void* d_out, int out_size) {
    const float* xyz = (const float*)d_in[0];
    float* out = (float*)d_out;
    (void)in_sizes; (void)n_in; (void)out_size;
    dimenet_r12_kernel<<<N_ATOMS / APB, 128>>>(xyz, out);
}

// round 13
// speedup vs baseline: 1.6933x; 1.4730x over previous
#include <cuda_runtime.h>
#include <math.h>
#include <stdint.h>

// DimeNet interaction fragment on the fixed circular graph from setup_inputs.
// Round 13: scalar acos-based angle (no cross product at all: u = dot/(d1*d2),
// alpha = acos(u) via sqrt(1-|u|)*poly + copysign), packed f32x2 accumulation
// on memory-native LDS.64 qwords. 256 threads, R8's bank-clean 24B rbf rows.

#define N_ATOMS 32768
#define ATOM_MASK (N_ATOMS - 1)
#define APB 16
#define PI_F   3.14159265358979323846f
#define PI_2_F 1.57079632679489661923f

static __device__ __forceinline__ uint64_t pk2(float lo, float hi) {
    uint64_t r; asm("mov.b64 %0, {%1, %2};" : "=l"(r) : "f"(lo), "f"(hi)); return r;
}
static __device__ __forceinline__ void fma2a(uint64_t& d, uint64_t a, uint64_t b) {
    asm("fma.rn.f32x2 %0, %1, %2, %0;" : "+l"(d) : "l"(a), "l"(b));
}

__global__ __launch_bounds__(256)
void dimenet_r13_kernel(const float* __restrict__ xyz, float* __restrict__ out) {
    // column-duplicated scalar tiles: row r holds data of column (r & 15)
    __shared__ float4 s_r4[APB][32];          // {rx,ry,rz,d}   8 KB
    __shared__ float  s_rbf[APB][32][6];      // 24B rows      12 KB (bank-clean)

    const int tid = threadIdx.x;
    const int a = tid >> 4;                   // atom slot 0..15
    const int c = tid & 15;                   // neighbor column
    const int j = blockIdx.x * APB + a;

    const int off = (c < 8) ? (c + 1) : (N_ATOMS - (c - 7));
    const int nb  = (j + off) & ATOM_MASK;

    const float jx = xyz[3 * j + 0];
    const float jy = xyz[3 * j + 1];
    const float jz = xyz[3 * j + 2];
    const float rx = xyz[3 * nb + 0] - jx;
    const float ry = xyz[3 * nb + 1] - jy;
    const float rz = xyz[3 * nb + 2] - jz;

    const float d2 = fmaf(rx, rx, fmaf(ry, ry, rz * rz));
    const float d  = d2 * rsqrtf(d2);
    const float4 my4 = make_float4(rx, ry, rz, d);
    s_r4[a][c] = my4;
    s_r4[a][c + 16] = my4;

    // radial basis (env-prescaled Chebyshev recurrence)
    const float x   = d * 0.2f;
    const float x2  = x * x;
    const float x5  = x2 * x2 * x;
    const float env = __fdividef(1.0f, x) + x5 * fmaf(x, fmaf(-21.0f, x, 48.0f), -28.0f);
    float sn, cs;
    __sincosf(PI_F * x, &sn, &cs);
    const float twoc = cs + cs;
    const float e1 = env * sn;
    const float e2 = twoc * e1;
    const float e3 = fmaf(twoc, e2, -e1);
    const float e4 = fmaf(twoc, e3, -e2);
    const float e5 = fmaf(twoc, e4, -e3);
    const float e6 = fmaf(twoc, e5, -e4);
    {
        float2* w  = (float2*)&s_rbf[a][c][0];
        float2* w2 = (float2*)&s_rbf[a][c + 16][0];
        const float2 f0 = make_float2(e1, e2);
        const float2 f1 = make_float2(e3, e4);
        const float2 f2 = make_float2(e5, e6);
        w[0] = f0;  w[1] = f1;  w[2] = f2;
        w2[0] = f0; w2[1] = f1; w2[2] = f2;
    }

    __syncwarp();   // produced & consumed within the same half-warp

    const float4*   rp   = &s_r4[a][c];                       // partner +k = rp[k]
    const uint64_t* rbfb = (const uint64_t*)&s_rbf[a][c][0];  // row +k = rbfb + 3k

    uint64_t acc0 = 0ull, acc1 = 0ull, acc2 = 0ull;           // packed over rbf comps

    // scalar acos-based angle: alpha = acos(dot / (|r1||r2|))
    //   t = sqrt(1-|u|) * poly(|u|)  (= acos(|u|), A&S 4.4.45)
    //   alpha = pi/2 - copysign(pi/2 - t, u)
    auto pair_alpha = [&](const float4 b) -> float {
        const float dot = fmaf(rx, b.x, fmaf(ry, b.y, rz * b.z));
        const float h   = d * b.w;                        // |r1||r2| > 0
        float u = __fdividef(dot, h);
        u = fminf(fmaxf(u, -1.0f), 1.0f);
        const float au = fabsf(u);
        const float s2 = fmaxf(1.0f - au, 1e-12f);
        const float s  = s2 * rsqrtf(s2);                 // sqrt(1-|u|)
        float p = fmaf(-0.0187293f, au, 0.0742610f);
        p = fmaf(p, au, -0.2121144f);
        p = fmaf(p, au, 1.5707288f);
        const float t = s * p;                            // acos(|u|) in [0, pi/2]
        return PI_2_F - copysignf(PI_2_F - t, u);
    };

    #pragma unroll
    for (int k = 1; k <= 7; k++) {
        const float alpha = pair_alpha(rp[k]);            // literal-offset LDS.128

        // own contribution: alpha * rbf[c+k]
        {
            const uint64_t al2 = pk2(alpha, alpha);
            fma2a(acc0, al2, rbfb[3 * k + 0]);
            fma2a(acc1, al2, rbfb[3 * k + 1]);
            fma2a(acc2, al2, rbfb[3 * k + 2]);
        }
        // mirror: alpha(c-k, c) from lane c-k; rbf row c-k = dup row c+16-k
        {
            const float alm = __shfl_sync(0xFFFFFFFFu, alpha, (c - k) & 15, 16);
            const uint64_t am2 = pk2(alm, alm);
            fma2a(acc0, am2, rbfb[3 * (16 - k) + 0]);
            fma2a(acc1, am2, rbfb[3 * (16 - k) + 1]);
            fma2a(acc2, am2, rbfb[3 * (16 - k) + 2]);
        }
    }
    // k = 8: pair is self-mirrored (both lanes compute identical alpha)
    {
        const float alpha = pair_alpha(rp[8]);
        const uint64_t al2 = pk2(alpha, alpha);
        fma2a(acc0, al2, rbfb[24]);
        fma2a(acc1, al2, rbfb[25]);
        fma2a(acc2, al2, rbfb[26]);
    }

    uint64_t* o = (uint64_t*)(out + (size_t)(j * 16 + c) * 6);
    o[0] = acc0;
    o[1] = acc1;
    o[2] = acc2;
}

extern "C" void kernel_launch(void* const* d_in, const int* in_sizes, int n_in,
                              void* d_out, int out_size) {
    const float* xyz = (const float*)d_in[0];
    float* out = (float*)d_out;
    (void)in_sizes; (void)n_in; (void)out_size;
    dimenet_r13_kernel<<<N_ATOMS / APB, 256>>>(xyz, out);
}